// round 3
// baseline (speedup 1.0000x reference)
#include <cuda_runtime.h>
#include <cstdint>

typedef unsigned long long ull;

#define NN_MAX 100000
#define LDIM 64
#define HD 32
#define EDIM 4
#define NCOL 36   // 32 (W1) + 4 (W_direct) fused columns

// Scratch: u[node][j] = sum_{k<64} x[node][k] * [W1 | Wd][k][j]
__device__ __align__(16) float g_u[NN_MAX * NCOL];
__device__ int g_idx_is64;   // 1 if edge_index is int64, 0 if int32

__device__ __forceinline__ ull pack2(float a) {
    ull r; asm("mov.b64 %0, {%1, %1};" : "=l"(r) : "f"(a)); return r;
}
__device__ __forceinline__ ull fma2(ull a, ull b, ull c) {
    ull d; asm("fma.rn.f32x2 %0, %1, %2, %3;" : "=l"(d) : "l"(a), "l"(b), "l"(c)); return d;
}
__device__ __forceinline__ void unpack2(ull v, float& lo, float& hi) {
    asm("mov.b64 {%0, %1}, %2;" : "=f"(lo), "=f"(hi) : "l"(v));
}

// ---------------------------------------------------------------------------
// Kernel 0: detect edge_index dtype. int32 data read as int64 combines two
// random indices -> value ~ idx_hi * 2^32, far outside [0, n_nodes).
// ---------------------------------------------------------------------------
__global__ void detect_idx_dtype(const void* ei, int n_nodes) {
    const long long* p = (const long long*)ei;
    bool all_ok = true;
    for (int i = 0; i < 64; i++) {
        long long v = p[i];
        if (v < 0 || v >= n_nodes) { all_ok = false; break; }
    }
    g_idx_is64 = all_ok ? 1 : 0;
}

// ---------------------------------------------------------------------------
// Kernel 1: per-node precompute u = x[:, :] @ [W1[:64] | Wd[:64]]
// ---------------------------------------------------------------------------
__global__ void __launch_bounds__(256) precompute_u(
    const float* __restrict__ x,
    const float* __restrict__ W1,
    const float* __restrict__ Wd,
    int n_nodes)
{
    __shared__ __align__(16) float sW[LDIM][NCOL];
    int tid = threadIdx.x;
    for (int i = tid; i < LDIM * NCOL; i += 256) {
        int k = i / NCOL, j = i - k * NCOL;
        sW[k][j] = (j < HD) ? W1[k * HD + j] : Wd[k * EDIM + (j - HD)];
    }
    __syncthreads();

    int node = blockIdx.x * 256 + tid;
    if (node >= n_nodes) return;

    float acc[NCOL];
    #pragma unroll
    for (int j = 0; j < NCOL; j++) acc[j] = 0.f;

    const float4* xr = (const float4*)(x + (size_t)node * LDIM);
    #pragma unroll 4
    for (int k4 = 0; k4 < LDIM / 4; k4++) {
        float4 v = __ldg(xr + k4);
        #pragma unroll
        for (int j = 0; j < NCOL; j++) {
            acc[j] = fmaf(v.x, sW[4 * k4 + 0][j], acc[j]);
            acc[j] = fmaf(v.y, sW[4 * k4 + 1][j], acc[j]);
            acc[j] = fmaf(v.z, sW[4 * k4 + 2][j], acc[j]);
            acc[j] = fmaf(v.w, sW[4 * k4 + 3][j], acc[j]);
        }
    }
    float4* ur = (float4*)(g_u + (size_t)node * NCOL);
    #pragma unroll
    for (int j4 = 0; j4 < NCOL / 4; j4++) {
        float4 r;
        r.x = acc[4 * j4 + 0]; r.y = acc[4 * j4 + 1];
        r.z = acc[4 * j4 + 2]; r.w = acc[4 * j4 + 3];
        ur[j4] = r;
    }
}

// ---------------------------------------------------------------------------
// Kernel 2: per-edge MLP.
//   a1 = u_s + u_t + max(x_s,x_t) @ Wdiff   (Wdiff = W[64:] - W[:64], 64x36)
//   h  = relu(a1[:32] + b1)
//   h2 = relu(h @ W2 + b2 + h)
//   out = h2 @ W3 + b3 + a1[32:36] + b_direct
// ---------------------------------------------------------------------------
__global__ void __launch_bounds__(256, 2) edge_kernel(
    const float* __restrict__ x,
    const void* __restrict__ ei,
    const float* __restrict__ W1, const float* __restrict__ b1,
    const float* __restrict__ Wd, const float* __restrict__ bd,
    const float* __restrict__ W2, const float* __restrict__ b2,
    const float* __restrict__ W3, const float* __restrict__ b3,
    float* __restrict__ out, int n_edges, int n_nodes)
{
    __shared__ __align__(16) float sWdiff[LDIM][NCOL];  // 9216 B
    __shared__ __align__(16) float sW2[HD][HD];         // 4096 B
    __shared__ __align__(16) float sW3[HD][EDIM];       //  512 B
    __shared__ float sb1[HD], sb2[HD], sbo[EDIM];

    int tid = threadIdx.x;
    for (int i = tid; i < LDIM * NCOL; i += 256) {
        int k = i / NCOL, j = i - k * NCOL;
        float hi, lo;
        if (j < HD) { hi = W1[(LDIM + k) * HD + j];        lo = W1[k * HD + j]; }
        else        { hi = Wd[(LDIM + k) * EDIM + (j-HD)]; lo = Wd[k * EDIM + (j-HD)]; }
        sWdiff[k][j] = hi - lo;
    }
    for (int i = tid; i < HD * HD; i += 256)  (&sW2[0][0])[i] = W2[i];
    for (int i = tid; i < HD * EDIM; i += 256)(&sW3[0][0])[i] = W3[i];
    if (tid < HD)  { sb1[tid] = b1[tid]; sb2[tid] = b2[tid]; }
    if (tid < EDIM) sbo[tid] = b3[tid] + bd[tid];
    __syncthreads();

    int e = blockIdx.x * 256 + tid;
    if (e >= n_edges) return;

    // ---- index load: dtype-flexible, clamped (never IMA) ----
    unsigned s, t;
    if (g_idx_is64) {
        s = (unsigned)((const long long*)ei)[e];
        t = (unsigned)((const long long*)ei)[(size_t)n_edges + e];
    } else {
        s = (unsigned)((const int*)ei)[e];
        t = (unsigned)((const int*)ei)[(size_t)n_edges + e];
    }
    unsigned nm1 = (unsigned)(n_nodes - 1);
    s = (s < nm1) ? s : nm1;
    t = (t < nm1) ? t : nm1;

    // ---- GEMM1: max(xs,xt) @ Wdiff, packed f32x2 accumulators ----
    ull acc[NCOL / 2];
    #pragma unroll
    for (int i = 0; i < NCOL / 2; i++) acc[i] = 0ULL;

    const float4* xs = (const float4*)(x + (size_t)s * LDIM);
    const float4* xt = (const float4*)(x + (size_t)t * LDIM);

    #pragma unroll 4
    for (int k4 = 0; k4 < LDIM / 4; k4++) {
        float4 a = __ldg(xs + k4);
        float4 b = __ldg(xt + k4);
        float m0 = fmaxf(a.x, b.x), m1 = fmaxf(a.y, b.y);
        float m2 = fmaxf(a.z, b.z), m3 = fmaxf(a.w, b.w);
        float m[4] = {m0, m1, m2, m3};
        #pragma unroll
        for (int kk = 0; kk < 4; kk++) {
            ull mm = pack2(m[kk]);
            const ulonglong2* wr = (const ulonglong2*)(&sWdiff[k4 * 4 + kk][0]);
            #pragma unroll
            for (int j4 = 0; j4 < NCOL / 4; j4++) {
                ulonglong2 w = wr[j4];
                acc[2 * j4 + 0] = fma2(mm, w.x, acc[2 * j4 + 0]);
                acc[2 * j4 + 1] = fma2(mm, w.y, acc[2 * j4 + 1]);
            }
        }
    }

    float c[NCOL];
    #pragma unroll
    for (int i = 0; i < NCOL / 2; i++) unpack2(acc[i], c[2 * i], c[2 * i + 1]);

    // add u_s + u_t
    const float4* us4 = (const float4*)(g_u + (size_t)s * NCOL);
    const float4* ut4 = (const float4*)(g_u + (size_t)t * NCOL);
    #pragma unroll
    for (int j4 = 0; j4 < NCOL / 4; j4++) {
        float4 uu = __ldg(us4 + j4);
        float4 vv = __ldg(ut4 + j4);
        c[4 * j4 + 0] += uu.x + vv.x;
        c[4 * j4 + 1] += uu.y + vv.y;
        c[4 * j4 + 2] += uu.z + vv.z;
        c[4 * j4 + 3] += uu.w + vv.w;
    }

    float h[HD];
    #pragma unroll
    for (int j = 0; j < HD; j++) h[j] = fmaxf(c[j] + sb1[j], 0.f);

    // ---- GEMM2: h @ W2, residual + relu ----
    ull acc2[HD / 2];
    #pragma unroll
    for (int i = 0; i < HD / 2; i++) acc2[i] = 0ULL;
    #pragma unroll 8
    for (int k = 0; k < HD; k++) {
        ull hk = pack2(h[k]);
        const ulonglong2* wr = (const ulonglong2*)(&sW2[k][0]);
        #pragma unroll
        for (int j4 = 0; j4 < HD / 4; j4++) {
            ulonglong2 w = wr[j4];
            acc2[2 * j4 + 0] = fma2(hk, w.x, acc2[2 * j4 + 0]);
            acc2[2 * j4 + 1] = fma2(hk, w.y, acc2[2 * j4 + 1]);
        }
    }
    float h2[HD];
    #pragma unroll
    for (int i = 0; i < HD / 2; i++) {
        float lo, hi; unpack2(acc2[i], lo, hi);
        h2[2 * i + 0] = fmaxf(lo + sb2[2 * i + 0] + h[2 * i + 0], 0.f);
        h2[2 * i + 1] = fmaxf(hi + sb2[2 * i + 1] + h[2 * i + 1], 0.f);
    }

    // ---- GEMM3: h2 @ W3 ----
    ull o01 = 0ULL, o23 = 0ULL;
    #pragma unroll 8
    for (int k = 0; k < HD; k++) {
        ull hk = pack2(h2[k]);
        ulonglong2 w = *(const ulonglong2*)(&sW3[k][0]);
        o01 = fma2(hk, w.x, o01);
        o23 = fma2(hk, w.y, o23);
    }
    float o0, o1, o2, o3;
    unpack2(o01, o0, o1);
    unpack2(o23, o2, o3);

    float4 r;
    r.x = o0 + c[HD + 0] + sbo[0];
    r.y = o1 + c[HD + 1] + sbo[1];
    r.z = o2 + c[HD + 2] + sbo[2];
    r.w = o3 + c[HD + 3] + sbo[3];
    ((float4*)out)[e] = r;
}

// ---------------------------------------------------------------------------
extern "C" void kernel_launch(void* const* d_in, const int* in_sizes, int n_in,
                              void* d_out, int out_size) {
    const float* x  = (const float*)d_in[0];
    const void*  ei = d_in[1];
    const float* Wd = (const float*)d_in[2];
    const float* bd = (const float*)d_in[3];
    const float* W1 = (const float*)d_in[4];
    const float* b1 = (const float*)d_in[5];
    const float* W2 = (const float*)d_in[6];
    const float* b2 = (const float*)d_in[7];
    const float* W3 = (const float*)d_in[8];
    const float* b3 = (const float*)d_in[9];
    float* out = (float*)d_out;

    int n_nodes = in_sizes[0] / LDIM;
    if (n_nodes > NN_MAX) n_nodes = NN_MAX;
    int n_edges = in_sizes[1] / 2;

    detect_idx_dtype<<<1, 1>>>(ei, n_nodes);
    precompute_u<<<(n_nodes + 255) / 256, 256>>>(x, W1, Wd, n_nodes);
    edge_kernel<<<(n_edges + 255) / 256, 256>>>(x, ei, W1, b1, Wd, bd,
                                                W2, b2, W3, b3, out, n_edges, n_nodes);
}